// round 1
// baseline (speedup 1.0000x reference)
#include <cuda_runtime.h>
#include <cstdint>

// PQLayer forward on GB300 (sm_103a).
//
// Key identity: codes = stop_gradient(hard - soft) + soft == hard (one-hot)
// numerically in the forward pass (exact for all zero entries). So:
//   k*[b,m]   = argmax_k <x[b, m*8:(m+1)*8], C[m,k,:]>
//   codes     = one_hot(k*)           (B, M, K)
//   x_hat     = C[m, k*, :]           (B, feat)
//
// Memory-bound: 1.07 GB of one-hot writes dominates. Compute uses packed
// fma.rn.f32x2 (FFMA2) with C[m] resident in registers per warp.

#define BB 16384
#define MM 64
#define KK 256
#define DD 8
#define FEAT (MM * DD)  // 512

using u64 = unsigned long long;

__device__ __forceinline__ u64 pack2(float lo, float hi) {
    u64 r;
    uint32_t a = __float_as_uint(lo), b = __float_as_uint(hi);
    asm("mov.b64 %0, {%1, %2};" : "=l"(r) : "r"(a), "r"(b));
    return r;
}

__device__ __forceinline__ void unpack2(u64 v, float& lo, float& hi) {
    uint32_t a, b;
    asm("mov.b64 {%0, %1}, %2;" : "=r"(a), "=r"(b) : "l"(v));
    lo = __uint_as_float(a);
    hi = __uint_as_float(b);
}

// Packed dual fp32 FMA (Blackwell FFMA2). IEEE fp32 per lane — identical
// numerics to two scalar FFMAs, half the fma-pipe issue slots.
__device__ __forceinline__ u64 fma2(u64 a, u64 b, u64 c) {
    u64 r;
    asm("fma.rn.f32x2 %0, %1, %2, %3;" : "=l"(r) : "l"(a), "l"(b), "l"(c));
    return r;
}

__device__ __forceinline__ float comp(const float4& v, int i) {
    return i == 0 ? v.x : i == 1 ? v.y : i == 2 ? v.z : v.w;
}

// grid = (M, B_CHUNKS), block = 128 (4 warps). Each block owns one subspace m
// and a contiguous range of b. Lane l of each warp owns codewords
// k in [8l, 8l+8), kept packed in registers for f32x2 FMA.
#define B_CHUNKS 64
#define BPB (BB / B_CHUNKS)  // 256 rows of b per block

__global__ void __launch_bounds__(128)
pq_forward_kernel(const float* __restrict__ x, const float* __restrict__ C,
                  float* __restrict__ xhat, float* __restrict__ codes)
{
    const int m    = blockIdx.x;
    const int lane = threadIdx.x & 31;
    const int w    = threadIdx.x >> 5;   // 0..3
    const int nw   = 4;

    // ---- Preload C[m, 8l .. 8l+8, :] into registers, packed in k-pairs ----
    // cp[j*8 + d] = { C[8l+2j][d], C[8l+2j+1][d] }  (j=0..3, d=0..7)
    u64 cp[32];
    {
        const float4* c4 =
            reinterpret_cast<const float4*>(C) + ((size_t)m * KK + 8 * lane) * 2;
        float4 ca[16];
#pragma unroll
        for (int t = 0; t < 16; t++) ca[t] = c4[t];  // k-off = t>>1, half = t&1
#pragma unroll
        for (int j = 0; j < 4; j++) {
#pragma unroll
            for (int d = 0; d < 8; d++) {
                float f0 = comp(ca[(2 * j)     * 2 + (d >> 2)], d & 3);
                float f1 = comp(ca[(2 * j + 1) * 2 + (d >> 2)], d & 3);
                cp[j * 8 + d] = pack2(f0, f1);
            }
        }
    }

    const float4* x4 = reinterpret_cast<const float4*>(x);
    const int iters = BPB / nw;  // 64
    int b = blockIdx.y * BPB + w;

    // Prefetch first x segment (8 floats, broadcast across the warp)
    float4 xa = x4[(size_t)b * (FEAT / 4) + m * 2];
    float4 xb = x4[(size_t)b * (FEAT / 4) + m * 2 + 1];

    for (int i = 0; i < iters; i++) {
        const int bn = b + nw;
        float4 xa_n = xa, xb_n = xb;
        if (i + 1 < iters) {  // prefetch next iteration's x
            xa_n = x4[(size_t)bn * (FEAT / 4) + m * 2];
            xb_n = x4[(size_t)bn * (FEAT / 4) + m * 2 + 1];
        }

        // ---- 8 dot products per lane via packed FMA (d-sequential order) ----
        u64 acc[4];
#pragma unroll
        for (int j = 0; j < 4; j++) acc[j] = 0ull;  // {+0, +0}
#pragma unroll
        for (int d = 0; d < 8; d++) {
            float xv = (d < 4) ? comp(xa, d) : comp(xb, d - 4);
            u64 xp = pack2(xv, xv);
#pragma unroll
            for (int j = 0; j < 4; j++) acc[j] = fma2(cp[j * 8 + d], xp, acc[j]);
        }

        // ---- local argmax over this lane's 8 codewords (ascending k) ----
        float bv;
        int bk;
        {
            float lo, hi;
            unpack2(acc[0], lo, hi);
            bv = lo; bk = 8 * lane;
            if (hi > bv) { bv = hi; bk = 8 * lane + 1; }
#pragma unroll
            for (int j = 1; j < 4; j++) {
                unpack2(acc[j], lo, hi);
                if (lo > bv) { bv = lo; bk = 8 * lane + 2 * j; }
                if (hi > bv) { bv = hi; bk = 8 * lane + 2 * j + 1; }
            }
        }

        // ---- warp argmax reduce (lowest k wins ties, matches jnp.argmax) ----
#pragma unroll
        for (int off = 16; off; off >>= 1) {
            float ov = __shfl_xor_sync(0xffffffffu, bv, off);
            int   ok = __shfl_xor_sync(0xffffffffu, bk, off);
            if (ov > bv || (ov == bv && ok < bk)) { bv = ov; bk = ok; }
        }

        // ---- write one-hot row: 2 fully-coalesced STG.128 per lane ----
        if (codes) {
            float4* crow =
                reinterpret_cast<float4*>(codes + ((size_t)b * MM + m) * KK);
            const int k0 = 4 * lane;
            float4 s0 = make_float4(k0 + 0 == bk ? 1.f : 0.f,
                                    k0 + 1 == bk ? 1.f : 0.f,
                                    k0 + 2 == bk ? 1.f : 0.f,
                                    k0 + 3 == bk ? 1.f : 0.f);
            const int k1 = 128 + 4 * lane;
            float4 s1 = make_float4(k1 + 0 == bk ? 1.f : 0.f,
                                    k1 + 1 == bk ? 1.f : 0.f,
                                    k1 + 2 == bk ? 1.f : 0.f,
                                    k1 + 3 == bk ? 1.f : 0.f);
            __stcs(&crow[lane],      s0);   // streaming: don't thrash L2
            __stcs(&crow[32 + lane], s1);
        }

        // ---- x_hat gather: lanes 0,1 copy the selected codeword ----
        if (xhat && lane < 2) {
            const float4* c4 = reinterpret_cast<const float4*>(C);
            float4 v = c4[((size_t)m * KK + bk) * 2 + lane];  // L1-hot
            __stcs(reinterpret_cast<float4*>(xhat) +
                       (size_t)b * (FEAT / 4) + m * 2 + lane, v);
        }

        b = bn; xa = xa_n; xb = xb_n;
    }
}

extern "C" void kernel_launch(void* const* d_in, const int* in_sizes, int n_in,
                              void* d_out, int out_size)
{
    // Inputs per metadata order: x (B*FEAT), C (M*K*D). Be robust to order.
    const float* x = (const float*)d_in[0];
    const float* C = (const float*)d_in[1];
    if (n_in >= 2 && in_sizes[0] == MM * KK * DD && in_sizes[1] == BB * FEAT) {
        x = (const float*)d_in[1];
        C = (const float*)d_in[0];
    }

    const long XHAT_N  = (long)BB * FEAT;        // 8,388,608
    const long CODES_N = (long)BB * MM * KK;     // 268,435,456

    float* xhat  = nullptr;
    float* codes = nullptr;
    if ((long)out_size >= XHAT_N + CODES_N) {
        xhat  = (float*)d_out;
        codes = (float*)d_out + XHAT_N;
    } else if ((long)out_size == CODES_N) {
        codes = (float*)d_out;
    } else {
        xhat = (float*)d_out;
    }

    dim3 grid(MM, B_CHUNKS);
    pq_forward_kernel<<<grid, 128>>>(x, C, xhat, codes);
}

// round 2
// speedup vs baseline: 1.4067x; 1.4067x over previous
#include <cuda_runtime.h>
#include <cstdint>

// PQLayer forward on GB300 (sm_103a) — v2: lane-per-b, C in smem, zero-stream + scatter.
//
// codes = stop_gradient(hard - soft) + soft == hard (one-hot) numerically.
//   k*[b,m] = argmax_k <x[b, m*8:(m+1)*8], C[m,k,:]>
//   codes   = one_hot(k*)  -> written as streamed zeros + scattered 1.0
//   x_hat   = C[m, k*, :]
//
// DRAM floor: ~1.14 GB traffic (1.07 GB one-hot writes) -> ~165 us @ ~7 TB/s.

#define BB 16384
#define MM 64
#define KK 256
#define DD 8
#define FEAT (MM * DD)          // 512
#define CHUNK_B 256             // b per block (8 warps x 32 lanes)

using u64 = unsigned long long;

__device__ __forceinline__ u64 pack2(float lo, float hi) {
    u64 r;
    uint32_t a = __float_as_uint(lo), b = __float_as_uint(hi);
    asm("mov.b64 %0, {%1, %2};" : "=l"(r) : "r"(a), "r"(b));
    return r;
}

__device__ __forceinline__ void unpack2(u64 v, float& lo, float& hi) {
    uint32_t a, b;
    asm("mov.b64 {%0, %1}, %2;" : "=r"(a), "=r"(b) : "l"(v));
    lo = __uint_as_float(a);
    hi = __uint_as_float(b);
}

// Packed dual fp32 FMA (Blackwell FFMA2): IEEE fp32 per lane.
__device__ __forceinline__ u64 fma2(u64 a, u64 b, u64 c) {
    u64 r;
    asm("fma.rn.f32x2 %0, %1, %2, %3;" : "=l"(r) : "l"(a), "l"(b), "l"(c));
    return r;
}

__global__ void __launch_bounds__(256, 5)
pq_forward_v2(const float* __restrict__ x, const float* __restrict__ C,
              float* __restrict__ xhat, float* __restrict__ codes)
{
    const int m    = blockIdx.x;
    const int tid  = threadIdx.x;
    const int lane = tid & 31;
    const int w    = tid >> 5;

    // smem: packed k-pair codebook + raw copy (for x_hat gather). 16 KB total.
    // cpk[j*8 + d] = { C[m][2j][d], C[m][2j+1][d] }   j=0..127, d=0..7
    __shared__ __align__(16) u64    cpk[128 * 8];
    __shared__ __align__(16) float4 craw[KK * 2];      // craw[k*2+h] = C[m][k][h*4..]

    // ---- stage C[m] (8 KB, coalesced) into both smem views ----
    {
        const float4* C4 = reinterpret_cast<const float4*>(C) + (size_t)m * (KK * 2);
        for (int q = tid; q < KK * 2; q += 256) {
            float4 f = C4[q];
            craw[q] = f;
            const int k = q >> 1, h = (q & 1) * 4;
            const int j = k >> 1, half = k & 1;
            float vals[4] = {f.x, f.y, f.z, f.w};
#pragma unroll
            for (int dd = 0; dd < 4; dd++)
                reinterpret_cast<uint32_t*>(&cpk[j * 8 + h + dd])[half] =
                    __float_as_uint(vals[dd]);
        }
    }
    __syncthreads();

    const int b0w = blockIdx.y * CHUNK_B + w * 32;   // warp's first b
    const int b   = b0w + lane;                      // this lane's b

    // ---- load x[b, m*8 .. m*8+8] and duplicate-pack for f32x2 ----
    const float4* x4 = reinterpret_cast<const float4*>(x) + (size_t)b * (FEAT / 4) + m * 2;
    const float4 xa = x4[0];
    const float4 xb = x4[1];
    u64 xp[8];
    xp[0] = pack2(xa.x, xa.x); xp[1] = pack2(xa.y, xa.y);
    xp[2] = pack2(xa.z, xa.z); xp[3] = pack2(xa.w, xa.w);
    xp[4] = pack2(xb.x, xb.x); xp[5] = pack2(xb.y, xb.y);
    xp[6] = pack2(xb.z, xb.z); xp[7] = pack2(xb.w, xb.w);

    // ---- stream zeros for this warp's 32 code rows (coalesced STG.128) ----
    // Issued before the k-loop so DRAM is busy while we compute.
    {
        const float4 z = make_float4(0.f, 0.f, 0.f, 0.f);
        float4* crow = reinterpret_cast<float4*>(codes) +
                       ((size_t)b0w * MM + m) * (KK / 4) + lane;
#pragma unroll 8
        for (int r = 0; r < 32; r++) {
            __stcs(crow, z);            // k[4*lane .. 4*lane+4)
            __stcs(crow + 32, z);       // k[128+4*lane .. )
            crow += MM * (KK / 4);      // next b, same m
        }
    }

    // ---- argmax over 256 codewords: 128 packed k-pairs ----
    float bv = -3.402823466e+38f;
    int   bk = 0;
#pragma unroll 8
    for (int j = 0; j < 128; j++) {
        const ulonglong2* cj = reinterpret_cast<const ulonglong2*>(&cpk[j * 8]);
        ulonglong2 c01 = cj[0], c23 = cj[1], c45 = cj[2], c67 = cj[3];
        u64 acc = 0ull;                 // {+0, +0}; d-sequential fp32 accumulation
        acc = fma2(c01.x, xp[0], acc);
        acc = fma2(c01.y, xp[1], acc);
        acc = fma2(c23.x, xp[2], acc);
        acc = fma2(c23.y, xp[3], acc);
        acc = fma2(c45.x, xp[4], acc);
        acc = fma2(c45.y, xp[5], acc);
        acc = fma2(c67.x, xp[6], acc);
        acc = fma2(c67.y, xp[7], acc);
        float lo, hi;
        unpack2(acc, lo, hi);
        if (lo > bv) { bv = lo; bk = 2 * j; }       // strict >: lowest k wins ties
        if (hi > bv) { bv = hi; bk = 2 * j + 1; }
    }

    // Order the zero stores before the 1.0 scatter (intra-warp fence).
    __syncwarp();

    // ---- scatter the single 1.0 per (b, m) row ----
    codes[((size_t)b * MM + m) * KK + bk] = 1.0f;

    // ---- x_hat: copy selected codeword C[m, bk, :] (smem-hot) ----
    const float4 v0 = craw[bk * 2];
    const float4 v1 = craw[bk * 2 + 1];
    float4* xh = reinterpret_cast<float4*>(xhat) + (size_t)b * (FEAT / 4) + m * 2;
    __stcs(xh,     v0);
    __stcs(xh + 1, v1);
}

extern "C" void kernel_launch(void* const* d_in, const int* in_sizes, int n_in,
                              void* d_out, int out_size)
{
    const float* x = (const float*)d_in[0];
    const float* C = (const float*)d_in[1];
    if (n_in >= 2 && in_sizes[0] == MM * KK * DD && in_sizes[1] == BB * FEAT) {
        x = (const float*)d_in[1];
        C = (const float*)d_in[0];
    }

    const long XHAT_N  = (long)BB * FEAT;        // 8,388,608
    const long CODES_N = (long)BB * MM * KK;     // 268,435,456

    float* xhat  = nullptr;
    float* codes = nullptr;
    if ((long)out_size >= XHAT_N + CODES_N) {
        xhat  = (float*)d_out;
        codes = (float*)d_out + XHAT_N;
    } else if ((long)out_size == CODES_N) {
        codes = (float*)d_out;
    } else {
        xhat = (float*)d_out;
    }

    dim3 grid(MM, BB / CHUNK_B);   // (64, 64)
    pq_forward_v2<<<grid, 256>>>(x, C, xhat, codes);
}